// round 1
// baseline (speedup 1.0000x reference)
#include <cuda_runtime.h>

#define H    128
#define FF   8
#define C4   512
#define MPAD 16
#define NT   256
#define NPAIR 7

// Pre-transposed recurrent weights: UT[c][k] = U[k][c], so each thread's
// columns are contiguous in k (LDG.128 friendly, L2-resident, 256KB each).
__device__ __align__(16) float g_UTe[C4 * H];
__device__ __align__(16) float g_UTd[C4 * H];

typedef unsigned long long u64;

__device__ __forceinline__ u64 dup2(float v) {
    u64 r; asm("mov.b64 %0, {%1, %1};" : "=l"(r) : "f"(v)); return r;
}
__device__ __forceinline__ void fma2(u64& d, u64 a, u64 b) {
    asm("fma.rn.f32x2 %0, %1, %2, %0;" : "+l"(d) : "l"(a), "l"(b));
}
__device__ __forceinline__ void unpack2(u64 v, float& lo, float& hi) {
    asm("mov.b64 {%0, %1}, %2;" : "=f"(lo), "=f"(hi) : "l"(v));
}
__device__ __forceinline__ float ex2f(float x){ float r; asm("ex2.approx.f32 %0, %1;" : "=f"(r) : "f"(x)); return r; }
__device__ __forceinline__ float rcpf(float x){ float r; asm("rcp.approx.f32 %0, %1;" : "=f"(r) : "f"(x)); return r; }
// sigmoid(x) = 1/(1+2^(-x*log2e)); saturates gracefully to {0,1} at +-inf
__device__ __forceinline__ float sigm(float x){ return rcpf(1.f + ex2f(-1.4426950408889634f * x)); }
// tanh(x) = 1 - 2/(1+2^(2x*log2e)); saturates gracefully to {-1,1}
__device__ __forceinline__ float tanhf_(float x){ return fmaf(-2.f, rcpf(1.f + ex2f(2.8853900817779268f * x)), 1.f); }

__global__ void transposeU_kernel(const float* __restrict__ Ue, const float* __restrict__ Ud) {
    int i = blockIdx.x * blockDim.x + threadIdx.x;
    if (i < H * C4) {
        int k = i / C4, c = i % C4;
        g_UTe[c * H + k] = Ue[i];
        g_UTd[c * H + k] = Ud[i];
    }
}

// Persistent batch-parallel LSTM autoencoder.
// One CTA per SM. CTA owns M (<=14) batch rows for the full 1024-step chain.
// Thread t owns gate-columns (t, t+256) of z and accumulates all 7 row-pairs
// with fma.rn.f32x2 (rows packed in the f32x2 lanes; h pair read as one
// broadcast LDS.64; u duplicated into both lanes).
__global__ void __launch_bounds__(NT, 1)
lstm_ae_kernel(const float* __restrict__ x,
               const float* __restrict__ We, const float* __restrict__ be,
               const float* __restrict__ Wd, const float* __restrict__ bd,
               const float* __restrict__ Wo, const float* __restrict__ bog,
               float* __restrict__ out, int B, int T)
{
    __shared__ float hsm[H][18];        // h[j][m], pad 18 keeps write conflicts 2-way
    __shared__ float zsm[C4][16];       // z[c][(m+c)&15] swizzle: conflict-free R/W
    __shared__ float xsm[FF][MPAD];     // current step input, transposed [f][m]
    __shared__ float wosm[H * FF];      // W_out staged once

    const int tid = threadIdx.x;
    const int nb  = gridDim.x;
    const int rs  = (int)(((long long)blockIdx.x * B) / nb);
    const int re  = (int)(((long long)(blockIdx.x + 1) * B) / nb);
    const int M   = re - rs;            // <= 14 guaranteed by launch config
    const int MH  = M * H;

    for (int i = tid; i < H * 18;   i += NT) (&hsm[0][0])[i] = 0.f;
    for (int i = tid; i < FF * MPAD; i += NT) (&xsm[0][0])[i] = 0.f;
    for (int i = tid; i < H * FF;   i += NT) wosm[i] = Wo[i];

    const int c0 = tid, c1 = tid + NT;  // this thread's two gate columns

    float cst[NPAIR];                   // cell state, fixed (m,j) ownership
    #pragma unroll
    for (int i = 0; i < NPAIR; i++) cst[i] = 0.f;

    const int  xm = tid >> 3, xf = tid & 7;
    const bool xthread = (tid < M * FF);
    const float bof = bog[xf];

    if (xthread) xsm[xf][xm] = x[(size_t)(rs + xm) * T * FF + xf];  // t = 0
    __syncthreads();

    for (int phase = 0; phase < 2; phase++) {
        const bool dec = (phase == 1);
        const float* UT = dec ? g_UTd : g_UTe;
        const float* Wm = dec ? Wd : We;
        const float* bv = dec ? bd : be;

        float wv0[FF], wv1[FF];
        #pragma unroll
        for (int f = 0; f < FF; f++) { wv0[f] = Wm[f * C4 + c0]; wv1[f] = Wm[f * C4 + c1]; }
        const float b0 = bv[c0], b1 = bv[c1];
        const float* u0p = UT + c0 * H;
        const float* u1p = UT + c1 * H;

        for (int t = 0; t < T; t++) {
            // ---- z = b + x@W + h@U  (FMA-pipe bound phase) ----
            u64 a0[NPAIR], a1[NPAIR];
            #pragma unroll
            for (int p = 0; p < NPAIR; p++) { a0[p] = dup2(b0); a1[p] = dup2(b1); }

            #pragma unroll
            for (int f = 0; f < FF; f++) {
                u64 w0 = dup2(wv0[f]), w1 = dup2(wv1[f]);
                #pragma unroll
                for (int p = 0; p < NPAIR; p++) {
                    u64 xp = *(const u64*)&xsm[f][2 * p];       // broadcast LDS.64
                    fma2(a0[p], xp, w0);
                    fma2(a1[p], xp, w1);
                }
            }

            #pragma unroll 4
            for (int k0 = 0; k0 < H; k0 += 4) {
                float4 u0 = *(const float4*)(u0p + k0);          // L2-hot LDG.128
                float4 u1 = *(const float4*)(u1p + k0);
                #pragma unroll
                for (int kk = 0; kk < 4; kk++) {
                    u64 d0 = dup2(((const float*)&u0)[kk]);
                    u64 d1 = dup2(((const float*)&u1)[kk]);
                    #pragma unroll
                    for (int p = 0; p < NPAIR; p++) {
                        u64 hp = *(const u64*)&hsm[k0 + kk][2 * p];  // broadcast LDS.64
                        fma2(a0[p], hp, d0);
                        fma2(a1[p], hp, d1);
                    }
                }
            }

            #pragma unroll
            for (int p = 0; p < NPAIR; p++) {
                float l0, h0v, l1, h1v;
                unpack2(a0[p], l0, h0v);
                unpack2(a1[p], l1, h1v);
                int s0 = (2 * p + c0) & 15;
                zsm[c0][s0] = l0; zsm[c0][(s0 + 1) & 15] = h0v;
                int s1 = (2 * p + c1) & 15;
                zsm[c1][s1] = l1; zsm[c1][(s1 + 1) & 15] = h1v;
            }
            __syncthreads();

            // ---- gates + state update (MUFU via ex2/rcp, ~1e-6 accurate) ----
            #pragma unroll
            for (int i = 0; i < NPAIR; i++) {
                int e = tid + NT * i;
                if (e < MH) {
                    int m = e >> 7, j = e & (H - 1);
                    int sl = (m + j) & 15;                       // 128g == 0 mod 16
                    float zi = zsm[j      ][sl];
                    float zf = zsm[j + 128][sl];
                    float zg = zsm[j + 256][sl];
                    float zo = zsm[j + 384][sl];
                    float ig = sigm(zi), fg = sigm(zf);
                    float gg = tanhf_(zg), og = sigm(zo);
                    float c  = fmaf(fg, cst[i], ig * gg);
                    cst[i] = c;
                    hsm[j][m] = og * tanhf_(c);
                }
            }

            if (!dec) {
                // prefetch next encoder input; after t = T-1 xsm keeps x[:,T-1,:]
                // which is exactly the decoder's initial y (reference semantics).
                if (xthread && t + 1 < T)
                    xsm[xf][xm] = x[(size_t)(rs + xm) * T * FF + (size_t)(t + 1) * FF + xf];
                __syncthreads();
            } else {
                __syncthreads();
                // ---- y = relu(h @ W_out + b_out), feed back + emit ----
                if (xthread) {
                    float acc0 = 0.f, acc1 = 0.f, acc2 = 0.f, acc3 = 0.f;
                    #pragma unroll 8
                    for (int k = 0; k < H; k += 4) {
                        acc0 = fmaf(hsm[k    ][xm], wosm[(k    ) * FF + xf], acc0);
                        acc1 = fmaf(hsm[k + 1][xm], wosm[(k + 1) * FF + xf], acc1);
                        acc2 = fmaf(hsm[k + 2][xm], wosm[(k + 2) * FF + xf], acc2);
                        acc3 = fmaf(hsm[k + 3][xm], wosm[(k + 3) * FF + xf], acc3);
                    }
                    float y = fmaxf(bof + ((acc0 + acc1) + (acc2 + acc3)), 0.f);
                    xsm[xf][xm] = y;
                    out[(size_t)(rs + xm) * T * FF + (size_t)t * FF + xf] = y;
                }
                __syncthreads();
            }
        }
    }
}

extern "C" void kernel_launch(void* const* d_in, const int* in_sizes, int n_in,
                              void* d_out, int out_size)
{
    const float* x  = (const float*)d_in[0];
    const float* We = (const float*)d_in[1];
    const float* Ue = (const float*)d_in[2];
    const float* be = (const float*)d_in[3];
    const float* Wd = (const float*)d_in[4];
    const float* Ud = (const float*)d_in[5];
    const float* bd = (const float*)d_in[6];
    const float* Wo = (const float*)d_in[7];
    const float* bo = (const float*)d_in[8];
    float* out = (float*)d_out;

    const int B = 2048;
    const int T = in_sizes[0] / (B * FF);

    transposeU_kernel<<<(H * C4 + 255) / 256, 256>>>(Ue, Ud);

    int dev = 0, nsm = 0;
    cudaGetDevice(&dev);
    cudaDeviceGetAttribute(&nsm, cudaDevAttrMultiProcessorCount, dev);
    int grid = nsm;
    const int mingrid = (B + 13) / 14;   // keep M <= 14 (NPAIR row-pairs cover 14 rows)
    if (grid < mingrid) grid = mingrid;  // correctness fallback if SM count is small
    if (grid > B) grid = B;

    lstm_ae_kernel<<<grid, NT>>>(x, We, be, Wd, bd, Wo, bo, out, B, T);
}

// round 2
// speedup vs baseline: 1.6643x; 1.6643x over previous
#include <cuda_runtime.h>

#define H    128
#define FF   8
#define C4   512
#define MB   16     // batch rows per CTA (2048 = 128 CTAs x 16, exact)
#define NT   256
#define NP   8      // f32x2 row-pairs per thread (16 rows)

// U re-blocked for coalesced loads: UB[((k>>2)*C4 + c)*4 + (k&3)].
// Thread handling column c loads float4 = U[4b..4b+3][c]; adjacent lanes
// (adjacent c) read adjacent 16B -> warp LDG.128 covers 4 lines only.
__device__ __align__(16) float g_UBe[C4 * H];
__device__ __align__(16) float g_UBd[C4 * H];

typedef unsigned long long u64;

__device__ __forceinline__ u64 dup2(float v) {
    u64 r; asm("mov.b64 %0, {%1, %1};" : "=l"(r) : "f"(v)); return r;
}
__device__ __forceinline__ void fma2(u64& d, u64 a, u64 b) {
    asm("fma.rn.f32x2 %0, %1, %2, %0;" : "+l"(d) : "l"(a), "l"(b));
}
__device__ __forceinline__ void unpack2(u64 v, float& lo, float& hi) {
    asm("mov.b64 {%0, %1}, %2;" : "=f"(lo), "=f"(hi) : "l"(v));
}
__device__ __forceinline__ float ex2f(float x){ float r; asm("ex2.approx.f32 %0, %1;" : "=f"(r) : "f"(x)); return r; }
__device__ __forceinline__ float rcpf(float x){ float r; asm("rcp.approx.f32 %0, %1;" : "=f"(r) : "f"(x)); return r; }
__device__ __forceinline__ float sigm(float x){ return rcpf(1.f + ex2f(-1.4426950408889634f * x)); }
__device__ __forceinline__ float tanhf_(float x){ return fmaf(-2.f, rcpf(1.f + ex2f(2.8853900817779268f * x)), 1.f); }

__global__ void transposeU_kernel(const float* __restrict__ Ue, const float* __restrict__ Ud) {
    int i = blockIdx.x * blockDim.x + threadIdx.x;
    if (i < H * C4) {
        int k = i / C4, c = i % C4;
        int idx = (((k >> 2) * C4) + c) * 4 + (k & 3);
        g_UBe[idx] = Ue[i];
        g_UBd[idx] = Ud[i];
    }
}

// Persistent batch-parallel LSTM autoencoder. One CTA owns 16 batch rows for
// all 1024 steps. Thread t owns gate columns (t, t+256); batch rows live in
// the f32x2 lanes (8 pairs). h read as LDS.128 broadcasts; U read coalesced.
__global__ void __launch_bounds__(NT, 1)
lstm_ae_kernel(const float* __restrict__ x,
               const float* __restrict__ We, const float* __restrict__ be,
               const float* __restrict__ Wd, const float* __restrict__ bd,
               const float* __restrict__ Wo, const float* __restrict__ bog,
               float* __restrict__ out, int T)
{
    __shared__ __align__(16) float hsm[H][MB];    // h[j][m]; stores & pair-reads conflict-free
    __shared__ __align__(16) float zsm[C4][MB];   // z[c][(m+c)&15] swizzle
    __shared__ __align__(16) float xsm[FF][MB];   // step input, [f][m]
    __shared__ float wosm[H * FF];

    const int tid = threadIdx.x;
    const int rs  = blockIdx.x * MB;

    for (int i = tid; i < H * MB; i += NT) (&hsm[0][0])[i] = 0.f;
    for (int i = tid; i < H * FF; i += NT) wosm[i] = Wo[i];

    const int c0 = tid, c1 = tid + NT;

    float cst[NP];
    #pragma unroll
    for (int p = 0; p < NP; p++) cst[p] = 0.f;

    const int  xm = tid >> 3, xf = tid & 7;
    const bool xth = tid < MB * FF;
    const float bof = bog[xf];

    if (xth) xsm[xf][xm] = x[(size_t)(rs + xm) * T * FF + xf];   // t = 0
    __syncthreads();

    for (int phase = 0; phase < 2; phase++) {
        const bool dec = (phase == 1);
        const float4* U4 = (const float4*)(dec ? g_UBd : g_UBe);
        const float*  Wm = dec ? Wd : We;
        const float*  bv = dec ? bd : be;

        u64 wd0[FF], wd1[FF];
        #pragma unroll
        for (int f = 0; f < FF; f++) {
            wd0[f] = dup2(Wm[f * C4 + c0]);
            wd1[f] = dup2(Wm[f * C4 + c1]);
        }
        const u64 bb0 = dup2(bv[c0]);
        const u64 bb1 = dup2(bv[c1]);

        for (int t = 0; t < T; t++) {
            // ---- z = b + x@W + h@U ----
            u64 a0[NP], a1[NP];
            #pragma unroll
            for (int p = 0; p < NP; p++) { a0[p] = bb0; a1[p] = bb1; }

            #pragma unroll
            for (int f = 0; f < FF; f++) {
                #pragma unroll
                for (int q = 0; q < 4; q++) {
                    ulonglong2 xp = *(const ulonglong2*)&xsm[f][4 * q];  // LDS.128 bcast
                    fma2(a0[2*q    ], xp.x, wd0[f]);
                    fma2(a0[2*q + 1], xp.y, wd0[f]);
                    fma2(a1[2*q    ], xp.x, wd1[f]);
                    fma2(a1[2*q + 1], xp.y, wd1[f]);
                }
            }

            float4 u0 = U4[c0];
            float4 u1 = U4[c1];
            #pragma unroll 2
            for (int blk = 0; blk < 31; blk++) {
                float4 n0 = U4[(size_t)(blk + 1) * C4 + c0];   // coalesced LDG.128
                float4 n1 = U4[(size_t)(blk + 1) * C4 + c1];
                #pragma unroll
                for (int kk = 0; kk < 4; kk++) {
                    const int k = blk * 4 + kk;
                    u64 d0 = dup2(((const float*)&u0)[kk]);
                    u64 d1 = dup2(((const float*)&u1)[kk]);
                    #pragma unroll
                    for (int q = 0; q < 4; q++) {
                        ulonglong2 hp = *(const ulonglong2*)&hsm[k][4 * q];  // LDS.128 bcast
                        fma2(a0[2*q    ], hp.x, d0);
                        fma2(a0[2*q + 1], hp.y, d0);
                        fma2(a1[2*q    ], hp.x, d1);
                        fma2(a1[2*q + 1], hp.y, d1);
                    }
                }
                u0 = n0; u1 = n1;
            }
            #pragma unroll
            for (int kk = 0; kk < 4; kk++) {                    // blk = 31 tail
                const int k = 124 + kk;
                u64 d0 = dup2(((const float*)&u0)[kk]);
                u64 d1 = dup2(((const float*)&u1)[kk]);
                #pragma unroll
                for (int q = 0; q < 4; q++) {
                    ulonglong2 hp = *(const ulonglong2*)&hsm[k][4 * q];
                    fma2(a0[2*q    ], hp.x, d0);
                    fma2(a0[2*q + 1], hp.y, d0);
                    fma2(a1[2*q    ], hp.x, d1);
                    fma2(a1[2*q + 1], hp.y, d1);
                }
            }

            // swizzled z exchange: slot(m, c) = (m + c) & 15 -> conflict-free R/W
            #pragma unroll
            for (int p = 0; p < NP; p++) {
                float l0, h0v; unpack2(a0[p], l0, h0v);
                float l1, h1v; unpack2(a1[p], l1, h1v);
                int s0 = (2 * p + c0) & 15;
                zsm[c0][s0] = l0; zsm[c0][(s0 + 1) & 15] = h0v;
                int s1 = (2 * p + c1) & 15;
                zsm[c1][s1] = l1; zsm[c1][(s1 + 1) & 15] = h1v;
            }
            __syncthreads();

            // ---- gates + state update; e -> (m = e&15, j = e>>4) keeps all
            //      z-reads and h-writes conflict-free ----
            #pragma unroll
            for (int i = 0; i < NP; i++) {
                int e = tid + NT * i;
                int m = e & 15, j = e >> 4;
                int sl = (m + j) & 15;                 // 128 == 0 mod 16
                float zi = zsm[j      ][sl];
                float zf = zsm[j + 128][sl];
                float zg = zsm[j + 256][sl];
                float zo = zsm[j + 384][sl];
                float ig = sigm(zi), fg = sigm(zf);
                float gg = tanhf_(zg), og = sigm(zo);
                float c  = fmaf(fg, cst[i], ig * gg);
                cst[i] = c;
                hsm[j][m] = og * tanhf_(c);
            }

            if (!dec) {
                if (xth && t + 1 < T)   // after t=T-1 xsm keeps x[:,T-1,:] = decoder y0
                    xsm[xf][xm] = x[(size_t)(rs + xm) * T * FF + (size_t)(t + 1) * FF + xf];
                __syncthreads();
            } else {
                __syncthreads();
                // ---- y = relu(h @ W_out + b_out); feed back + emit ----
                if (xth) {
                    float a = 0.f, b2 = 0.f, c2 = 0.f, d2 = 0.f;
                    #pragma unroll 8
                    for (int k = 0; k < H; k += 4) {
                        a  = fmaf(hsm[k    ][xm], wosm[(k    ) * FF + xf], a);
                        b2 = fmaf(hsm[k + 1][xm], wosm[(k + 1) * FF + xf], b2);
                        c2 = fmaf(hsm[k + 2][xm], wosm[(k + 2) * FF + xf], c2);
                        d2 = fmaf(hsm[k + 3][xm], wosm[(k + 3) * FF + xf], d2);
                    }
                    float y = fmaxf(bof + ((a + b2) + (c2 + d2)), 0.f);
                    xsm[xf][xm] = y;
                    out[(size_t)(rs + xm) * T * FF + (size_t)t * FF + xf] = y;
                }
                __syncthreads();
            }
        }
    }
}

extern "C" void kernel_launch(void* const* d_in, const int* in_sizes, int n_in,
                              void* d_out, int out_size)
{
    const float* x  = (const float*)d_in[0];
    const float* We = (const float*)d_in[1];
    const float* Ue = (const float*)d_in[2];
    const float* be = (const float*)d_in[3];
    const float* Wd = (const float*)d_in[4];
    const float* Ud = (const float*)d_in[5];
    const float* bd = (const float*)d_in[6];
    const float* Wo = (const float*)d_in[7];
    const float* bo = (const float*)d_in[8];
    float* out = (float*)d_out;

    const int B = 2048;
    const int T = in_sizes[0] / (B * FF);

    transposeU_kernel<<<(H * C4 + 255) / 256, 256>>>(Ue, Ud);
    lstm_ae_kernel<<<B / MB, NT>>>(x, We, be, Wd, bd, Wo, bo, out, T);
}

// round 3
// speedup vs baseline: 1.6702x; 1.0035x over previous
#include <cuda_runtime.h>

#define H    128
#define FF   8
#define C4   512
#define MB   16     // batch rows per CTA (2048 = 128 CTAs x 16, exact)
#define NT   256
#define NP   8      // f32x2 row-pairs per thread (16 rows)

// U re-blocked for coalesced loads: UB[((k>>2)*C4 + c)*4 + (k&3)].
// Thread handling column c loads float4 = U[4b..4b+3][c]; adjacent lanes
// (adjacent c) read adjacent 16B -> warp LDG.128 covers 4 lines only.
__device__ __align__(16) float g_UBe[C4 * H];
__device__ __align__(16) float g_UBd[C4 * H];

typedef unsigned long long u64;

__device__ __forceinline__ u64 dup2(float v) {
    u64 r; asm("mov.b64 %0, {%1, %1};" : "=l"(r) : "f"(v)); return r;
}
__device__ __forceinline__ void fma2(u64& d, u64 a, u64 b) {
    asm("fma.rn.f32x2 %0, %1, %2, %0;" : "+l"(d) : "l"(a), "l"(b));
}
__device__ __forceinline__ void unpack2(u64 v, float& lo, float& hi) {
    asm("mov.b64 {%0, %1}, %2;" : "=f"(lo), "=f"(hi) : "l"(v));
}
__device__ __forceinline__ float ex2f(float x){ float r; asm("ex2.approx.f32 %0, %1;" : "=f"(r) : "f"(x)); return r; }
__device__ __forceinline__ float rcpf(float x){ float r; asm("rcp.approx.f32 %0, %1;" : "=f"(r) : "f"(x)); return r; }
__device__ __forceinline__ float sigm(float x){ return rcpf(1.f + ex2f(-1.4426950408889634f * x)); }
__device__ __forceinline__ float tanhf_(float x){ return fmaf(-2.f, rcpf(1.f + ex2f(2.8853900817779268f * x)), 1.f); }

__global__ void transposeU_kernel(const float* __restrict__ Ue, const float* __restrict__ Ud) {
    int i = blockIdx.x * blockDim.x + threadIdx.x;
    if (i < H * C4) {
        int k = i / C4, c = i % C4;
        int idx = (((k >> 2) * C4) + c) * 4 + (k & 3);
        g_UBe[idx] = Ue[i];
        g_UBd[idx] = Ud[i];
    }
}

// Persistent batch-parallel LSTM autoencoder. One CTA owns 16 batch rows for
// all 1024 steps. Thread t owns gate columns (t, t+256); batch rows live in
// the f32x2 lanes (8 pairs). h read as LDS.128 broadcasts; U read coalesced.
__global__ void __launch_bounds__(NT, 1)
lstm_ae_kernel(const float* __restrict__ x,
               const float* __restrict__ We, const float* __restrict__ be,
               const float* __restrict__ Wd, const float* __restrict__ bd,
               const float* __restrict__ Wo, const float* __restrict__ bog,
               float* __restrict__ out, int T)
{
    __shared__ __align__(16) float hsm[H][MB];    // h[j][m]; stores & pair-reads conflict-free
    __shared__ __align__(16) float zsm[C4][MB];   // z[c][(m+c)&15] swizzle
    __shared__ __align__(16) float xsm[FF][MB];   // step input, [f][m]
    __shared__ float wosm[H * FF];

    const int tid = threadIdx.x;
    const int rs  = blockIdx.x * MB;

    for (int i = tid; i < H * MB; i += NT) (&hsm[0][0])[i] = 0.f;
    for (int i = tid; i < H * FF; i += NT) wosm[i] = Wo[i];

    const int c0 = tid, c1 = tid + NT;

    float cst[NP];
    #pragma unroll
    for (int p = 0; p < NP; p++) cst[p] = 0.f;

    const int  xm = tid >> 3, xf = tid & 7;
    const bool xth = tid < MB * FF;
    const float bof = bog[xf];

    if (xth) xsm[xf][xm] = x[(size_t)(rs + xm) * T * FF + xf];   // t = 0
    __syncthreads();

    for (int phase = 0; phase < 2; phase++) {
        const bool dec = (phase == 1);
        const float4* U4 = (const float4*)(dec ? g_UBd : g_UBe);
        const float*  Wm = dec ? Wd : We;
        const float*  bv = dec ? bd : be;

        u64 wd0[FF], wd1[FF];
        #pragma unroll
        for (int f = 0; f < FF; f++) {
            wd0[f] = dup2(Wm[f * C4 + c0]);
            wd1[f] = dup2(Wm[f * C4 + c1]);
        }
        const u64 bb0 = dup2(bv[c0]);
        const u64 bb1 = dup2(bv[c1]);

        for (int t = 0; t < T; t++) {
            // ---- z = b + x@W + h@U ----
            u64 a0[NP], a1[NP];
            #pragma unroll
            for (int p = 0; p < NP; p++) { a0[p] = bb0; a1[p] = bb1; }

            #pragma unroll
            for (int f = 0; f < FF; f++) {
                #pragma unroll
                for (int q = 0; q < 4; q++) {
                    ulonglong2 xp = *(const ulonglong2*)&xsm[f][4 * q];  // LDS.128 bcast
                    fma2(a0[2*q    ], xp.x, wd0[f]);
                    fma2(a0[2*q + 1], xp.y, wd0[f]);
                    fma2(a1[2*q    ], xp.x, wd1[f]);
                    fma2(a1[2*q + 1], xp.y, wd1[f]);
                }
            }

            float4 u0 = U4[c0];
            float4 u1 = U4[c1];
            #pragma unroll 2
            for (int blk = 0; blk < 31; blk++) {
                float4 n0 = U4[(size_t)(blk + 1) * C4 + c0];   // coalesced LDG.128
                float4 n1 = U4[(size_t)(blk + 1) * C4 + c1];
                #pragma unroll
                for (int kk = 0; kk < 4; kk++) {
                    const int k = blk * 4 + kk;
                    u64 d0 = dup2(((const float*)&u0)[kk]);
                    u64 d1 = dup2(((const float*)&u1)[kk]);
                    #pragma unroll
                    for (int q = 0; q < 4; q++) {
                        ulonglong2 hp = *(const ulonglong2*)&hsm[k][4 * q];  // LDS.128 bcast
                        fma2(a0[2*q    ], hp.x, d0);
                        fma2(a0[2*q + 1], hp.y, d0);
                        fma2(a1[2*q    ], hp.x, d1);
                        fma2(a1[2*q + 1], hp.y, d1);
                    }
                }
                u0 = n0; u1 = n1;
            }
            #pragma unroll
            for (int kk = 0; kk < 4; kk++) {                    // blk = 31 tail
                const int k = 124 + kk;
                u64 d0 = dup2(((const float*)&u0)[kk]);
                u64 d1 = dup2(((const float*)&u1)[kk]);
                #pragma unroll
                for (int q = 0; q < 4; q++) {
                    ulonglong2 hp = *(const ulonglong2*)&hsm[k][4 * q];
                    fma2(a0[2*q    ], hp.x, d0);
                    fma2(a0[2*q + 1], hp.y, d0);
                    fma2(a1[2*q    ], hp.x, d1);
                    fma2(a1[2*q + 1], hp.y, d1);
                }
            }

            // swizzled z exchange: slot(m, c) = (m + c) & 15 -> conflict-free R/W
            #pragma unroll
            for (int p = 0; p < NP; p++) {
                float l0, h0v; unpack2(a0[p], l0, h0v);
                float l1, h1v; unpack2(a1[p], l1, h1v);
                int s0 = (2 * p + c0) & 15;
                zsm[c0][s0] = l0; zsm[c0][(s0 + 1) & 15] = h0v;
                int s1 = (2 * p + c1) & 15;
                zsm[c1][s1] = l1; zsm[c1][(s1 + 1) & 15] = h1v;
            }
            __syncthreads();

            // ---- gates + state update; e -> (m = e&15, j = e>>4) keeps all
            //      z-reads and h-writes conflict-free ----
            #pragma unroll
            for (int i = 0; i < NP; i++) {
                int e = tid + NT * i;
                int m = e & 15, j = e >> 4;
                int sl = (m + j) & 15;                 // 128 == 0 mod 16
                float zi = zsm[j      ][sl];
                float zf = zsm[j + 128][sl];
                float zg = zsm[j + 256][sl];
                float zo = zsm[j + 384][sl];
                float ig = sigm(zi), fg = sigm(zf);
                float gg = tanhf_(zg), og = sigm(zo);
                float c  = fmaf(fg, cst[i], ig * gg);
                cst[i] = c;
                hsm[j][m] = og * tanhf_(c);
            }

            if (!dec) {
                if (xth && t + 1 < T)   // after t=T-1 xsm keeps x[:,T-1,:] = decoder y0
                    xsm[xf][xm] = x[(size_t)(rs + xm) * T * FF + (size_t)(t + 1) * FF + xf];
                __syncthreads();
            } else {
                __syncthreads();
                // ---- y = relu(h @ W_out + b_out); feed back + emit ----
                if (xth) {
                    float a = 0.f, b2 = 0.f, c2 = 0.f, d2 = 0.f;
                    #pragma unroll 8
                    for (int k = 0; k < H; k += 4) {
                        a  = fmaf(hsm[k    ][xm], wosm[(k    ) * FF + xf], a);
                        b2 = fmaf(hsm[k + 1][xm], wosm[(k + 1) * FF + xf], b2);
                        c2 = fmaf(hsm[k + 2][xm], wosm[(k + 2) * FF + xf], c2);
                        d2 = fmaf(hsm[k + 3][xm], wosm[(k + 3) * FF + xf], d2);
                    }
                    float y = fmaxf(bof + ((a + b2) + (c2 + d2)), 0.f);
                    xsm[xf][xm] = y;
                    out[(size_t)(rs + xm) * T * FF + (size_t)t * FF + xf] = y;
                }
                __syncthreads();
            }
        }
    }
}

extern "C" void kernel_launch(void* const* d_in, const int* in_sizes, int n_in,
                              void* d_out, int out_size)
{
    const float* x  = (const float*)d_in[0];
    const float* We = (const float*)d_in[1];
    const float* Ue = (const float*)d_in[2];
    const float* be = (const float*)d_in[3];
    const float* Wd = (const float*)d_in[4];
    const float* Ud = (const float*)d_in[5];
    const float* bd = (const float*)d_in[6];
    const float* Wo = (const float*)d_in[7];
    const float* bo = (const float*)d_in[8];
    float* out = (float*)d_out;

    const int B = 2048;
    const int T = in_sizes[0] / (B * FF);

    transposeU_kernel<<<(H * C4 + 255) / 256, 256>>>(Ue, Ud);
    lstm_ae_kernel<<<B / MB, NT>>>(x, We, be, Wd, bd, Wo, bo, out, T);
}